// round 10
// baseline (speedup 1.0000x reference)
#include <cuda_runtime.h>
#include <math.h>
#include <limits.h>

#define Nn 30000
#define Ee 400000
#define C1n 15000
#define E2n 100000
#define C2n 7500
#define Bn 16

#define T1S 168   // T1 row stride (162 used)
#define K1 162    // 150 w1b + 6 b1b + 6 root1
#define T2S 864   // T2 row stride
#define K2 864    // 800 w2b + 32 b2b + 32 root2

typedef unsigned long long ull;

// ---------------- zero-init block (single memset 0) ---------------------------
struct ZBlk {
    int   degD1[Nn];
    int   degD2[C1n], cntc1[C1n];
    float possum[C1n * 3];
    float gsum[Bn * 64];
    float gcnt[Bn];
    float maxabs;
};
// ---------------- 0xff-init block (single memset 0xff) ------------------------
struct FBlk {
    float xp[C1n * 32];      // 0xffffffff sentinel (loses to all atomicMaxFloat)
    float x3[C2n * 64];
    int   batchp[C1n];       // -1
    int   batch2[C2n];       // -1
};
__device__ ZBlk gz;
__device__ FBlk gf;

// ---------------- uninitialized scratch ----------------------------------------
__device__ int g_offD1[Nn + 1], g_curD1[Nn];
__device__ int g_offD2[C1n + 1], g_curD2[C1n];
__device__ __align__(16) float4 g_e4[Ee];          // {ea0,ea1,ea2, src-bits} dst-sorted
__device__ int g_csrD2s[E2n];                      // src ids dst-sorted
__device__ __align__(16) float g_T1[(size_t)Nn * T1S];
__device__ __align__(16) float g_T2[(size_t)C1n * T2S];

__device__ __forceinline__ void atomicMaxFloat(float* addr, float val) {
    if (val >= 0.f) atomicMax((int*)addr, __float_as_int(val));
    else            atomicMin((unsigned int*)addr, __float_as_uint(val));
}
__device__ __forceinline__ float elu1(float v) { return v > 0.f ? v : expm1f(v); }
__device__ __forceinline__ float fixneg(float v) { return (v > -3e38f) ? v : 0.f; }

__device__ __forceinline__ ull fma2(ull a, ull b, ull c) {
    ull d;
    asm("fma.rn.f32x2 %0, %1, %2, %3;" : "=l"(d) : "l"(a), "l"(b), "l"(c));
    return d;
}
__device__ __forceinline__ void unpack2f(float& a, float& b, ull v) {
    asm("mov.b64 {%0, %1}, %2;" : "=f"(a), "=f"(b) : "l"(v));
}

// ---------------- K1: degree histograms ----------------------------------------
__global__ void k_hist(const int* __restrict__ ei, const int* __restrict__ ei2,
                       const int* __restrict__ cl1) {
    int t = blockIdx.x * blockDim.x + threadIdx.x;
    if (t < Ee)  atomicAdd(&gz.degD1[ei[Ee + t]], 1);
    if (t < E2n) atomicAdd(&gz.degD2[ei2[E2n + t]], 1);
    if (t < Nn)  atomicAdd(&gz.cntc1[cl1[t]], 1);
}

// ---------------- K2: exclusive scans (2 arrays, 1 block each) ------------------
__global__ void k_scan() {
    const int* deg; int* off; int* cur; int n;
    if (blockIdx.x == 0) { deg = gz.degD1; off = g_offD1; cur = g_curD1; n = Nn; }
    else                 { deg = gz.degD2; off = g_offD2; cur = g_curD2; n = C1n; }
    __shared__ int wsum[32];
    __shared__ int carry;
    int tid = threadIdx.x, lane = tid & 31, wid = tid >> 5;
    if (tid == 0) carry = 0;
    __syncthreads();
    for (int base = 0; base < n; base += 1024) {
        int idx = base + tid;
        int v = (idx < n) ? deg[idx] : 0;
        int incl = v;
#pragma unroll
        for (int o = 1; o < 32; o <<= 1) {
            int tt = __shfl_up_sync(0xffffffffu, incl, o);
            if (lane >= o) incl += tt;
        }
        if (lane == 31) wsum[wid] = incl;
        __syncthreads();
        if (wid == 0) {
            int s = wsum[lane];
#pragma unroll
            for (int o = 1; o < 32; o <<= 1) {
                int tt = __shfl_up_sync(0xffffffffu, s, o);
                if (lane >= o) s += tt;
            }
            wsum[lane] = s;
        }
        __syncthreads();
        int woff = (wid == 0) ? 0 : wsum[wid - 1];
        int c0 = carry;
        if (idx < n) { int ex = c0 + woff + incl - v; off[idx] = ex; cur[idx] = ex; }
        __syncthreads();
        if (tid == 0) carry = c0 + wsum[31];
        __syncthreads();
    }
    if (threadIdx.x == 0) off[n] = carry;
}

// ---------------- K3: scatter (dst-sorted edge payloads) ------------------------
__global__ void k_scat(const int* __restrict__ ei, const int* __restrict__ ei2,
                       const float* __restrict__ ea) {
    int t = blockIdx.x * blockDim.x + threadIdx.x;
    if (t < Ee) {
        int p = atomicAdd(&g_curD1[ei[Ee + t]], 1);
        float4 v;
        v.x = ea[3 * t]; v.y = ea[3 * t + 1]; v.z = ea[3 * t + 2];
        v.w = __int_as_float(ei[t]);
        g_e4[p] = v;
    }
    if (t < E2n) {
        int p = atomicAdd(&g_curD2[ei2[E2n + t]], 1);
        g_csrD2s[p] = ei2[t];
    }
}

// ---------------- K4: conv1 edge pass -> T1 (warp per dst, pipelined) -----------
__global__ void __launch_bounds__(256) k_conv1(
        const float* __restrict__ x, const float* __restrict__ pos,
        const int* __restrict__ batch, const int* __restrict__ cl1,
        const float* __restrict__ w1a, const float* __restrict__ b1a) {
    int tid = threadIdx.x;
    int d = (blockIdx.x * blockDim.x + tid) >> 5;
    int lane = tid & 31;
    if (d >= Nn) return;
    float wa0 = 0.f, wa1 = 0.f, wa2 = 0.f, ba = 0.f;
    if (lane < 25) { wa0 = w1a[lane]; wa1 = w1a[25 + lane]; wa2 = w1a[50 + lane]; ba = b1a[lane]; }
    else if (lane == 25) ba = 1.f;   // h == 1 -> x-sum (bias) row
    float acc0 = 0.f, acc1 = 0.f, acc2 = 0.f, acc3 = 0.f, acc4 = 0.f, acc5 = 0.f;
    int p0 = g_offD1[d], p1 = g_offD1[d + 1];
    float4 cur = make_float4(0.f, 0.f, 0.f, 0.f);
    float2 xa = make_float2(0.f, 0.f), xb = xa, xc = xa;
    if (p0 < p1) {
        cur = g_e4[p0];
        const float2* xs = (const float2*)(x + __float_as_int(cur.w) * 6);
        xa = xs[0]; xb = xs[1]; xc = xs[2];
    }
    for (int p = p0; p < p1; p++) {
        float4 nxt = cur;
        float2 na = xa, nb = xb, nc = xc;
        if (p + 1 < p1) {
            nxt = g_e4[p + 1];
            const float2* xs = (const float2*)(x + __float_as_int(nxt.w) * 6);
            na = xs[0]; nb = xs[1]; nc = xs[2];
        }
        float h = fmaxf(fmaf(cur.x, wa0, fmaf(cur.y, wa1, fmaf(cur.z, wa2, ba))), 0.f);
        acc0 = fmaf(h, xa.x, acc0); acc1 = fmaf(h, xa.y, acc1);
        acc2 = fmaf(h, xb.x, acc2); acc3 = fmaf(h, xb.y, acc3);
        acc4 = fmaf(h, xc.x, acc4); acc5 = fmaf(h, xc.y, acc5);
        cur = nxt; xa = na; xb = nb; xc = nc;
    }
    float invd = 1.f / fmaxf((float)(p1 - p0), 1.f);
    float* Trow = g_T1 + (size_t)d * T1S + lane * 6;
    if (lane < 26) {
        Trow[0] = acc0 * invd; Trow[1] = acc1 * invd; Trow[2] = acc2 * invd;
        Trow[3] = acc3 * invd; Trow[4] = acc4 * invd; Trow[5] = acc5 * invd;
    } else if (lane == 26) {
#pragma unroll
        for (int i = 0; i < 6; i++) Trow[i] = x[d * 6 + i];
    } else if (lane == 27) {
        atomicMax(&gf.batchp[cl1[d]], batch[d]);
    } else if (lane >= 29) {
        atomicAdd(&gz.possum[cl1[d] * 3 + (lane - 29)], pos[d * 3 + (lane - 29)]);
    }
}

// ---------------- K5: gemm1  out = T1 @ [w1b|b1b|root1] + bias1 -> elu -> pool1 --
__global__ void __launch_bounds__(256) k_gemm1(
        const float* __restrict__ w1b, const float* __restrict__ b1b,
        const float* __restrict__ root1, const float* __restrict__ bias1,
        const int* __restrict__ cl1) {
    __shared__ __align__(16) float Ws[192 * 32];
    __shared__ __align__(16) float Ts[32 * 136];
    int tid = threadIdx.x;
    int nb = blockIdx.x * 128;
    for (int idx = tid; idx < 192 * 32; idx += 256) {
        float v = 0.f;
        if (idx < 4800)      v = w1b[idx];
        else if (idx < 4992) v = b1b[idx - 4800];
        else if (idx < 5184) v = root1[idx - 4992];
        Ws[idx] = v;
    }
    int cg = tid & 7, ng = tid >> 3;
    int c4 = cg * 4, n4 = ng * 4;
    float acc[4][4];
#pragma unroll
    for (int a = 0; a < 4; a++)
#pragma unroll
        for (int b = 0; b < 4; b++) acc[a][b] = 0.f;
    for (int kk = 0; kk < K1; kk += 32) {
        __syncthreads();
        for (int idx = tid; idx < 128 * 32; idx += 256) {
            int n = idx >> 5, k = idx & 31;
            float v = 0.f;
            if (kk + k < K1 && nb + n < Nn) v = g_T1[(size_t)(nb + n) * T1S + kk + k];
            Ts[k * 136 + n] = v;
        }
        __syncthreads();
#pragma unroll 8
        for (int k = 0; k < 32; k++) {
            float4 tv = *(const float4*)&Ts[k * 136 + n4];
            float4 wv = *(const float4*)&Ws[(kk + k) * 32 + c4];
            float ta[4] = {tv.x, tv.y, tv.z, tv.w};
            float wa[4] = {wv.x, wv.y, wv.z, wv.w};
#pragma unroll
            for (int a = 0; a < 4; a++)
#pragma unroll
                for (int b = 0; b < 4; b++) acc[a][b] = fmaf(ta[a], wa[b], acc[a][b]);
        }
    }
#pragma unroll
    for (int a = 0; a < 4; a++) {
        int n = nb + n4 + a;
        if (n >= Nn) continue;
        int c = cl1[n];
#pragma unroll
        for (int b = 0; b < 4; b++) {
            float v = elu1(acc[a][b] + bias1[c4 + b]);
            atomicMaxFloat(&gf.xp[c * 32 + c4 + b], v);
        }
    }
}

// ---------------- K6: global max |cart| ----------------------------------------
__global__ void k_maxabs(const int* __restrict__ ei2) {
    int e = blockIdx.x * blockDim.x + threadIdx.x;
    float m = 0.f;
    if (e < E2n) {
        int s = ei2[e], d = ei2[E2n + e];
        float is = 1.f / fmaxf((float)gz.cntc1[s], 1.f);
        float id = 1.f / fmaxf((float)gz.cntc1[d], 1.f);
#pragma unroll
        for (int k = 0; k < 3; k++)
            m = fmaxf(m, fabsf(gz.possum[s * 3 + k] * is - gz.possum[d * 3 + k] * id));
    }
#pragma unroll
    for (int o = 16; o; o >>= 1) m = fmaxf(m, __shfl_xor_sync(0xffffffffu, m, o));
    if ((threadIdx.x & 31) == 0) atomicMax((int*)&gz.maxabs, __float_as_int(m));
}

// ---------------- K7: conv2 edge pass -> T2 (warp per dst C1 node) ---------------
__global__ void __launch_bounds__(256) k_conv2(
        const float* __restrict__ w2a, const float* __restrict__ b2a) {
    int tid = threadIdx.x;
    int d = (blockIdx.x * blockDim.x + tid) >> 5;
    int lane = tid & 31;
    if (d >= C1n) return;
    float wa0 = 0.f, wa1 = 0.f, wa2 = 0.f, ba = 0.f;
    if (lane < 25) { wa0 = w2a[lane]; wa1 = w2a[25 + lane]; wa2 = w2a[50 + lane]; ba = b2a[lane]; }
    else if (lane == 25) ba = 1.f;
    float invcd = 1.f / fmaxf((float)gz.cntc1[d], 1.f);
    float pd0 = gz.possum[d * 3] * invcd, pd1 = gz.possum[d * 3 + 1] * invcd,
          pd2 = gz.possum[d * 3 + 2] * invcd;
    float inv = 0.5f / gz.maxabs;
    float acc[26];
#pragma unroll
    for (int r = 0; r < 26; r++) acc[r] = 0.f;
    int p0 = g_offD2[d], p1 = g_offD2[d + 1];
    for (int p = p0; p < p1; p++) {
        int src = g_csrD2s[p];
        float invcs = 1.f / fmaxf((float)gz.cntc1[src], 1.f);
        float e0 = fmaf(gz.possum[src * 3] * invcs - pd0,     inv, 0.5f);
        float e1 = fmaf(gz.possum[src * 3 + 1] * invcs - pd1, inv, 0.5f);
        float e2 = fmaf(gz.possum[src * 3 + 2] * invcs - pd2, inv, 0.5f);
        float h = fmaxf(fmaf(e0, wa0, fmaf(e1, wa1, fmaf(e2, wa2, ba))), 0.f);
        float xpi = fixneg(gf.xp[src * 32 + lane]);
#pragma unroll
        for (int r = 0; r < 26; r++) {
            float hr = __shfl_sync(0xffffffffu, h, r);
            acc[r] = fmaf(hr, xpi, acc[r]);
        }
    }
    float invd = 1.f / fmaxf((float)(p1 - p0), 1.f);
    float* Trow = g_T2 + (size_t)d * T2S;
#pragma unroll
    for (int r = 0; r < 26; r++) Trow[r * 32 + lane] = acc[r] * invd;
    Trow[832 + lane] = fixneg(gf.xp[d * 32 + lane]);   // root columns
}

// ---------------- K8: gemm2 via packed f32x2  (pairs (c, c+32)) ------------------
// 128 threads; 64-node x 32-k tiles; thread = 4 nodes x 4 pairs.
__global__ void __launch_bounds__(128) k_gemm2(
        const float* __restrict__ w2b, const float* __restrict__ b2b,
        const float* __restrict__ root2, const float* __restrict__ bias2,
        const int* __restrict__ cl2) {
    __shared__ __align__(16) float wsp[32 * 64];     // [k][pair c][2] = W[k][c+32s]
    __shared__ __align__(16) float2 td[32 * 66];     // [k][n] duplicated, EVEN stride (16B-aligned rows)
    int tid = threadIdx.x;
    int nb = blockIdx.x * 64;
    int cg = tid & 7, ng = tid >> 3;     // 8 pair-groups x 16 node-groups
    int c4 = cg * 4, n4 = ng * 4;
    ull acc[4][4];
#pragma unroll
    for (int a = 0; a < 4; a++)
#pragma unroll
        for (int b = 0; b < 4; b++) acc[a][b] = 0ULL;
    for (int kk = 0; kk < K2; kk += 32) {
        __syncthreads();
        for (int idx = tid; idx < 2048; idx += 128) {
            // Ws: j = c*2+s  ->  W[kk+k][c + 32*s]
            int k = idx >> 6, j = idx & 63;
            int c = j >> 1, s = j & 1;
            int kg = kk + k;
            int col = c + 32 * s;
            float wv;
            if (kg < 800)      wv = w2b[kg * 64 + col];
            else if (kg < 832) wv = b2b[(kg - 800) * 64 + col];
            else               wv = root2[(kg - 832) * 64 + col];
            wsp[k * 64 + j] = wv;
            // Ts: n-major so k runs contiguous in gmem (coalesced)
            int n = idx >> 5, kt = idx & 31;
            float tv = (nb + n < C1n) ? g_T2[(size_t)(nb + n) * T2S + kk + kt] : 0.f;
            td[kt * 66 + n] = make_float2(tv, tv);
        }
        __syncthreads();
#pragma unroll 8
        for (int k = 0; k < 32; k++) {
            ulonglong2 tA = *(const ulonglong2*)&td[k * 66 + n4];
            ulonglong2 tB = *(const ulonglong2*)&td[k * 66 + n4 + 2];
            ulonglong2 wA = *(const ulonglong2*)&wsp[k * 64 + c4 * 2];
            ulonglong2 wB = *(const ulonglong2*)&wsp[k * 64 + c4 * 2 + 4];
            ull tp[4] = {tA.x, tA.y, tB.x, tB.y};
            ull wp[4] = {wA.x, wA.y, wB.x, wB.y};
#pragma unroll
            for (int a = 0; a < 4; a++)
#pragma unroll
                for (int b = 0; b < 4; b++) acc[a][b] = fma2(tp[a], wp[b], acc[a][b]);
        }
    }
#pragma unroll
    for (int a = 0; a < 4; a++) {
        int n = nb + n4 + a;
        if (n >= C1n) continue;
        int c2 = cl2[n];
#pragma unroll
        for (int b = 0; b < 4; b++) {
            float lo, hi;
            unpack2f(lo, hi, acc[a][b]);
            float v0 = elu1(lo + bias2[c4 + b]);
            float v1 = elu1(hi + bias2[c4 + b + 32]);
            atomicMaxFloat(&gf.x3[c2 * 64 + c4 + b], v0);
            atomicMaxFloat(&gf.x3[c2 * 64 + c4 + b + 32], v1);
        }
        if (cg == 0) atomicMax(&gf.batch2[c2], max(gf.batchp[n], 0));
    }
}

// ---------------- K9: pool2 finalize + global mean scatter ----------------------
__global__ void k_pool2() {
    int c = (blockIdx.x * blockDim.x + threadIdx.x) >> 5;
    int lane = threadIdx.x & 31;
    if (c >= C2n) return;
    float v0 = fixneg(gf.x3[c * 64 + lane]);
    float v1 = fixneg(gf.x3[c * 64 + lane + 32]);
    int b = max(gf.batch2[c], 0);
    atomicAdd(&gz.gsum[b * 64 + lane], v0);
    atomicAdd(&gz.gsum[b * 64 + lane + 32], v1);
    if (lane == 0) atomicAdd(&gz.gcnt[b], 1.f);
}

// ---------------- K10: FC head + log_softmax ------------------------------------
__global__ void k_head(const float* __restrict__ fc1w, const float* __restrict__ fc1b,
                       const float* __restrict__ fc2w, const float* __restrict__ fc2b,
                       float* __restrict__ out) {
    __shared__ float g[16 * 64];
    __shared__ float hh[16 * 128];
    __shared__ float lg[16 * 10];
    int tid = threadIdx.x;
    for (int i = tid; i < 16 * 64; i += 256) g[i] = gz.gsum[i] / fmaxf(gz.gcnt[i >> 6], 1.f);
    __syncthreads();
    for (int o = tid; o < 16 * 128; o += 256) {
        int b = o >> 7, j = o & 127;
        float acc = fc1b[j];
        for (int k = 0; k < 64; k++) acc = fmaf(g[b * 64 + k], fc1w[k * 128 + j], acc);
        hh[o] = elu1(acc);
    }
    __syncthreads();
    if (tid < 160) {
        int b = tid / 10, k = tid % 10;
        float acc = fc2b[k];
        for (int j = 0; j < 128; j++) acc = fmaf(hh[b * 128 + j], fc2w[j * 10 + k], acc);
        lg[tid] = acc;
    }
    __syncthreads();
    if (tid < 16) {
        float m = -1e30f;
        for (int k = 0; k < 10; k++) m = fmaxf(m, lg[tid * 10 + k]);
        float s = 0.f;
        for (int k = 0; k < 10; k++) s += expf(lg[tid * 10 + k] - m);
        float ls = logf(s) + m;
        for (int k = 0; k < 10; k++) out[tid * 10 + k] = lg[tid * 10 + k] - ls;
    }
}

// ---------------- host launcher --------------------------------------------------
extern "C" void kernel_launch(void* const* d_in, const int* in_sizes, int n_in,
                              void* d_out, int out_size) {
    const float *x, *ea, *pos, *w1a, *b1a, *w1b, *b1b, *root1, *bias1;
    const float *w2a, *b2a, *w2b, *b2b, *root2, *bias2, *fc1w, *fc1b, *fc2w, *fc2b;
    const int *ei, *batch, *cl1, *ei2, *cl2;

    if (in_sizes[3] == 2 * Ee) {
        x = (const float*)d_in[0];  ea = (const float*)d_in[1];  pos = (const float*)d_in[2];
        ei = (const int*)d_in[3];   batch = (const int*)d_in[4]; cl1 = (const int*)d_in[5];
        ei2 = (const int*)d_in[6];  cl2 = (const int*)d_in[7];
        w1a = (const float*)d_in[8];  b1a = (const float*)d_in[9];
        w1b = (const float*)d_in[10]; b1b = (const float*)d_in[11];
        root1 = (const float*)d_in[12]; bias1 = (const float*)d_in[13];
        w2a = (const float*)d_in[14]; b2a = (const float*)d_in[15];
        w2b = (const float*)d_in[16]; b2b = (const float*)d_in[17];
        root2 = (const float*)d_in[18]; bias2 = (const float*)d_in[19];
        fc1w = (const float*)d_in[20]; fc1b = (const float*)d_in[21];
        fc2w = (const float*)d_in[22]; fc2b = (const float*)d_in[23];
    } else {
        x = (const float*)d_in[0];  ea = (const float*)d_in[1];  pos = (const float*)d_in[2];
        w1a = (const float*)d_in[3];  b1a = (const float*)d_in[4];
        w1b = (const float*)d_in[5];  b1b = (const float*)d_in[6];
        root1 = (const float*)d_in[7]; bias1 = (const float*)d_in[8];
        w2a = (const float*)d_in[9];  b2a = (const float*)d_in[10];
        w2b = (const float*)d_in[11]; b2b = (const float*)d_in[12];
        root2 = (const float*)d_in[13]; bias2 = (const float*)d_in[14];
        fc1w = (const float*)d_in[15]; fc1b = (const float*)d_in[16];
        fc2w = (const float*)d_in[17]; fc2b = (const float*)d_in[18];
        ei = (const int*)d_in[19];  batch = (const int*)d_in[20]; cl1 = (const int*)d_in[21];
        ei2 = (const int*)d_in[22]; cl2 = (const int*)d_in[23];
    }

    void *pz = nullptr, *pf = nullptr;
    cudaGetSymbolAddress(&pz, gz);
    cudaGetSymbolAddress(&pf, gf);
    cudaMemsetAsync(pz, 0, sizeof(ZBlk));
    cudaMemsetAsync(pf, 0xff, sizeof(FBlk));

    k_hist<<<(Ee + 255) / 256, 256>>>(ei, ei2, cl1);
    k_scan<<<2, 1024>>>();
    k_scat<<<(Ee + 255) / 256, 256>>>(ei, ei2, ea);
    k_conv1<<<3750, 256>>>(x, pos, batch, cl1, w1a, b1a);
    k_gemm1<<<(Nn + 127) / 128, 256>>>(w1b, b1b, root1, bias1, cl1);
    k_maxabs<<<(E2n + 255) / 256, 256>>>(ei2);
    k_conv2<<<1875, 256>>>(w2a, b2a);
    k_gemm2<<<(C1n + 63) / 64, 128>>>(w2b, b2b, root2, bias2, cl2);
    k_pool2<<<938, 256>>>();
    k_head<<<1, 256>>>(fc1w, fc1b, fc2w, fc2b, (float*)d_out);
}

// round 11
// speedup vs baseline: 1.1191x; 1.1191x over previous
#include <cuda_runtime.h>
#include <math.h>
#include <limits.h>

#define Nn 30000
#define Ee 400000
#define C1n 15000
#define E2n 100000
#define C2n 7500
#define Bn 16

#define T1S 168   // T1 row stride (162 used)
#define K1 162    // 150 w1b + 6 b1b + 6 root1
#define T2S 864   // T2 row stride
#define K2 864    // 800 w2b + 32 b2b + 32 root2

typedef unsigned long long ull;

// ---------------- zero-init block (single memset 0) ---------------------------
struct ZBlk {
    int   degD1[Nn];
    int   degD2[C1n], cntc1[C1n];
    float possum[C1n * 3];
    float gsum[Bn * 64];
    float gcnt[Bn];
    float maxabs;
};
// ---------------- 0xff-init block (single memset 0xff) ------------------------
struct FBlk {
    float xp[C1n * 32];      // 0xffffffff sentinel (loses to all atomicMaxFloat)
    float x3[C2n * 64];
    int   batchp[C1n];       // -1
    int   batch2[C2n];       // -1
};
__device__ ZBlk gz;
__device__ FBlk gf;

// ---------------- uninitialized scratch ----------------------------------------
__device__ int g_offD1[Nn + 1], g_curD1[Nn];
__device__ int g_offD2[C1n + 1], g_curD2[C1n];
__device__ __align__(16) float4 g_e4[Ee];          // {ea0,ea1,ea2, src-bits} dst-sorted
__device__ int g_csrD2s[E2n];                      // src ids dst-sorted
__device__ __align__(16) float g_T1[(size_t)Nn * T1S];
__device__ __align__(16) float g_T2[(size_t)C1n * T2S];

__device__ __forceinline__ void atomicMaxFloat(float* addr, float val) {
    if (val >= 0.f) atomicMax((int*)addr, __float_as_int(val));
    else            atomicMin((unsigned int*)addr, __float_as_uint(val));
}
__device__ __forceinline__ float elu1(float v) { return v > 0.f ? v : expm1f(v); }
__device__ __forceinline__ float fixneg(float v) { return (v > -3e38f) ? v : 0.f; }

__device__ __forceinline__ ull fma2(ull a, ull b, ull c) {
    ull d;
    asm("fma.rn.f32x2 %0, %1, %2, %3;" : "=l"(d) : "l"(a), "l"(b), "l"(c));
    return d;
}
__device__ __forceinline__ void unpack2f(float& a, float& b, ull v) {
    asm("mov.b64 {%0, %1}, %2;" : "=f"(a), "=f"(b) : "l"(v));
}

// ---------------- K1: histograms + pool-input scatters --------------------------
__global__ void k_hist(const int* __restrict__ ei, const int* __restrict__ ei2,
                       const int* __restrict__ cl1, const float* __restrict__ pos,
                       const int* __restrict__ batch) {
    int t = blockIdx.x * blockDim.x + threadIdx.x;
    if (t < Ee)  atomicAdd(&gz.degD1[ei[Ee + t]], 1);
    if (t < E2n) atomicAdd(&gz.degD2[ei2[E2n + t]], 1);
    if (t < Nn) {
        int c = cl1[t];
        atomicAdd(&gz.cntc1[c], 1);
        atomicAdd(&gz.possum[c * 3],     pos[t * 3]);
        atomicAdd(&gz.possum[c * 3 + 1], pos[t * 3 + 1]);
        atomicAdd(&gz.possum[c * 3 + 2], pos[t * 3 + 2]);
        atomicMax(&gf.batchp[c], batch[t]);
    }
}

// ---------------- K2: exclusive scans (2 arrays, 4 elems/thread) ----------------
__global__ void k_scan() {
    const int* deg; int* off; int* cur; int n;
    if (blockIdx.x == 0) { deg = gz.degD1; off = g_offD1; cur = g_curD1; n = Nn; }
    else                 { deg = gz.degD2; off = g_offD2; cur = g_curD2; n = C1n; }
    __shared__ int wsum[32];
    __shared__ int carry;
    int tid = threadIdx.x, lane = tid & 31, wid = tid >> 5;
    if (tid == 0) carry = 0;
    __syncthreads();
    for (int base = 0; base < n; base += 4096) {
        int i0 = base + tid * 4;
        int v[4];
#pragma unroll
        for (int k = 0; k < 4; k++) v[k] = (i0 + k < n) ? deg[i0 + k] : 0;
        int s = v[0] + v[1] + v[2] + v[3];
        int incl = s;
#pragma unroll
        for (int o = 1; o < 32; o <<= 1) {
            int tt = __shfl_up_sync(0xffffffffu, incl, o);
            if (lane >= o) incl += tt;
        }
        if (lane == 31) wsum[wid] = incl;
        __syncthreads();
        if (wid == 0) {
            int t2 = wsum[lane];
#pragma unroll
            for (int o = 1; o < 32; o <<= 1) {
                int tt = __shfl_up_sync(0xffffffffu, t2, o);
                if (lane >= o) t2 += tt;
            }
            wsum[lane] = t2;
        }
        __syncthreads();
        int woff = (wid == 0) ? 0 : wsum[wid - 1];
        int run = carry + woff + incl - s;
#pragma unroll
        for (int k = 0; k < 4; k++) {
            if (i0 + k < n) { off[i0 + k] = run; cur[i0 + k] = run; }
            run += v[k];
        }
        __syncthreads();
        if (tid == 0) carry += wsum[31];
        __syncthreads();
    }
    if (threadIdx.x == 0) off[n] = carry;
}

// ---------------- K3: scatter (dst-sorted edge payloads) ------------------------
__global__ void k_scat(const int* __restrict__ ei, const int* __restrict__ ei2,
                       const float* __restrict__ ea) {
    int t = blockIdx.x * blockDim.x + threadIdx.x;
    if (t < Ee) {
        int p = atomicAdd(&g_curD1[ei[Ee + t]], 1);
        float4 v;
        v.x = ea[3 * t]; v.y = ea[3 * t + 1]; v.z = ea[3 * t + 2];
        v.w = __int_as_float(ei[t]);
        g_e4[p] = v;
    }
    if (t < E2n) {
        int p = atomicAdd(&g_curD2[ei2[E2n + t]], 1);
        g_csrD2s[p] = ei2[t];
    }
}

// ---------------- K4: conv1 edge pass -> T1 (warp per dst node) -----------------
__global__ void __launch_bounds__(256) k_conv1(
        const float* __restrict__ x,
        const float* __restrict__ w1a, const float* __restrict__ b1a) {
    int tid = threadIdx.x;
    int d = (blockIdx.x * blockDim.x + tid) >> 5;
    int lane = tid & 31;
    if (d >= Nn) return;
    float wa0 = 0.f, wa1 = 0.f, wa2 = 0.f, ba = 0.f;
    if (lane < 25) { wa0 = w1a[lane]; wa1 = w1a[25 + lane]; wa2 = w1a[50 + lane]; ba = b1a[lane]; }
    else if (lane == 25) ba = 1.f;   // h == 1 -> x-sum (bias) row
    float acc0 = 0.f, acc1 = 0.f, acc2 = 0.f, acc3 = 0.f, acc4 = 0.f, acc5 = 0.f;
    int p0 = g_offD1[d], p1 = g_offD1[d + 1];
    for (int p = p0; p < p1; p++) {
        float4 e4 = g_e4[p];
        int src = __float_as_int(e4.w);
        const float2* xs = (const float2*)(x + src * 6);
        float2 x01 = xs[0], x23 = xs[1], x45 = xs[2];
        float h = fmaxf(fmaf(e4.x, wa0, fmaf(e4.y, wa1, fmaf(e4.z, wa2, ba))), 0.f);
        acc0 = fmaf(h, x01.x, acc0); acc1 = fmaf(h, x01.y, acc1);
        acc2 = fmaf(h, x23.x, acc2); acc3 = fmaf(h, x23.y, acc3);
        acc4 = fmaf(h, x45.x, acc4); acc5 = fmaf(h, x45.y, acc5);
    }
    float invd = 1.f / fmaxf((float)(p1 - p0), 1.f);
    float* Trow = g_T1 + (size_t)d * T1S + lane * 6;
    if (lane < 26) {
        Trow[0] = acc0 * invd; Trow[1] = acc1 * invd; Trow[2] = acc2 * invd;
        Trow[3] = acc3 * invd; Trow[4] = acc4 * invd; Trow[5] = acc5 * invd;
    } else if (lane == 26) {
#pragma unroll
        for (int i = 0; i < 6; i++) Trow[i] = x[d * 6 + i];
    }
}

// ---------------- K5: gemm1  out = T1 @ [w1b|b1b|root1] + bias1 -> elu -> pool1 --
__global__ void __launch_bounds__(256) k_gemm1(
        const float* __restrict__ w1b, const float* __restrict__ b1b,
        const float* __restrict__ root1, const float* __restrict__ bias1,
        const int* __restrict__ cl1) {
    __shared__ __align__(16) float Ws[192 * 32];
    __shared__ __align__(16) float Ts[32 * 136];
    int tid = threadIdx.x;
    int nb = blockIdx.x * 128;
    for (int idx = tid; idx < 192 * 32; idx += 256) {
        float v = 0.f;
        if (idx < 4800)      v = w1b[idx];
        else if (idx < 4992) v = b1b[idx - 4800];
        else if (idx < 5184) v = root1[idx - 4992];
        Ws[idx] = v;
    }
    int cg = tid & 7, ng = tid >> 3;
    int c4 = cg * 4, n4 = ng * 4;
    float acc[4][4];
#pragma unroll
    for (int a = 0; a < 4; a++)
#pragma unroll
        for (int b = 0; b < 4; b++) acc[a][b] = 0.f;
    for (int kk = 0; kk < K1; kk += 32) {
        __syncthreads();
        for (int idx = tid; idx < 128 * 32; idx += 256) {
            int n = idx >> 5, k = idx & 31;
            float v = 0.f;
            if (kk + k < K1 && nb + n < Nn) v = g_T1[(size_t)(nb + n) * T1S + kk + k];
            Ts[k * 136 + n] = v;
        }
        __syncthreads();
#pragma unroll 8
        for (int k = 0; k < 32; k++) {
            float4 tv = *(const float4*)&Ts[k * 136 + n4];
            float4 wv = *(const float4*)&Ws[(kk + k) * 32 + c4];
            float ta[4] = {tv.x, tv.y, tv.z, tv.w};
            float wa[4] = {wv.x, wv.y, wv.z, wv.w};
#pragma unroll
            for (int a = 0; a < 4; a++)
#pragma unroll
                for (int b = 0; b < 4; b++) acc[a][b] = fmaf(ta[a], wa[b], acc[a][b]);
        }
    }
#pragma unroll
    for (int a = 0; a < 4; a++) {
        int n = nb + n4 + a;
        if (n >= Nn) continue;
        int c = cl1[n];
#pragma unroll
        for (int b = 0; b < 4; b++) {
            float v = elu1(acc[a][b] + bias1[c4 + b]);
            atomicMaxFloat(&gf.xp[c * 32 + c4 + b], v);
        }
    }
}

// ---------------- K6: global max |cart| ----------------------------------------
__global__ void k_maxabs(const int* __restrict__ ei2) {
    int e = blockIdx.x * blockDim.x + threadIdx.x;
    float m = 0.f;
    if (e < E2n) {
        int s = ei2[e], d = ei2[E2n + e];
        float is = 1.f / fmaxf((float)gz.cntc1[s], 1.f);
        float id = 1.f / fmaxf((float)gz.cntc1[d], 1.f);
#pragma unroll
        for (int k = 0; k < 3; k++)
            m = fmaxf(m, fabsf(gz.possum[s * 3 + k] * is - gz.possum[d * 3 + k] * id));
    }
#pragma unroll
    for (int o = 16; o; o >>= 1) m = fmaxf(m, __shfl_xor_sync(0xffffffffu, m, o));
    if ((threadIdx.x & 31) == 0) atomicMax((int*)&gz.maxabs, __float_as_int(m));
}

// ---------------- K7: conv2 edge pass -> T2 (warp per dst C1 node) ---------------
__global__ void __launch_bounds__(256) k_conv2(
        const float* __restrict__ w2a, const float* __restrict__ b2a) {
    int tid = threadIdx.x;
    int d = (blockIdx.x * blockDim.x + tid) >> 5;
    int lane = tid & 31;
    if (d >= C1n) return;
    float wa0 = 0.f, wa1 = 0.f, wa2 = 0.f, ba = 0.f;
    if (lane < 25) { wa0 = w2a[lane]; wa1 = w2a[25 + lane]; wa2 = w2a[50 + lane]; ba = b2a[lane]; }
    else if (lane == 25) ba = 1.f;
    float invcd = 1.f / fmaxf((float)gz.cntc1[d], 1.f);
    float pd0 = gz.possum[d * 3] * invcd, pd1 = gz.possum[d * 3 + 1] * invcd,
          pd2 = gz.possum[d * 3 + 2] * invcd;
    float inv = 0.5f / gz.maxabs;
    float acc[26];
#pragma unroll
    for (int r = 0; r < 26; r++) acc[r] = 0.f;
    int p0 = g_offD2[d], p1 = g_offD2[d + 1];
    for (int p = p0; p < p1; p++) {
        int src = g_csrD2s[p];
        float invcs = 1.f / fmaxf((float)gz.cntc1[src], 1.f);
        float e0 = fmaf(gz.possum[src * 3] * invcs - pd0,     inv, 0.5f);
        float e1 = fmaf(gz.possum[src * 3 + 1] * invcs - pd1, inv, 0.5f);
        float e2 = fmaf(gz.possum[src * 3 + 2] * invcs - pd2, inv, 0.5f);
        float h = fmaxf(fmaf(e0, wa0, fmaf(e1, wa1, fmaf(e2, wa2, ba))), 0.f);
        float xpi = fixneg(gf.xp[src * 32 + lane]);
#pragma unroll
        for (int r = 0; r < 26; r++) {
            float hr = __shfl_sync(0xffffffffu, h, r);
            acc[r] = fmaf(hr, xpi, acc[r]);
        }
    }
    float invd = 1.f / fmaxf((float)(p1 - p0), 1.f);
    float* Trow = g_T2 + (size_t)d * T2S;
#pragma unroll
    for (int r = 0; r < 26; r++) Trow[r * 32 + lane] = acc[r] * invd;
    Trow[832 + lane] = fixneg(gf.xp[d * 32 + lane]);   // root columns
}

// ---------------- K8: gemm2 via packed f32x2, 256 thr, 128-node tile -------------
// pairs (c, c+32); thread = 4 nodes x 4 pairs; smem ~41KB.
__global__ void __launch_bounds__(256) k_gemm2(
        const float* __restrict__ w2b, const float* __restrict__ b2b,
        const float* __restrict__ root2, const float* __restrict__ bias2,
        const int* __restrict__ cl2) {
    __shared__ __align__(16) float wsp[32 * 64];      // [k][pair c][2] = W[k][c+32s]
    __shared__ __align__(16) float2 td[32 * 130];     // [k][n] duplicated, even stride
    int tid = threadIdx.x;
    int nb = blockIdx.x * 128;
    int cg = tid & 7, ng = tid >> 3;      // 8 pair-groups x 32 node-groups
    int c4 = cg * 4, n4 = ng * 4;
    ull acc[4][4];
#pragma unroll
    for (int a = 0; a < 4; a++)
#pragma unroll
        for (int b = 0; b < 4; b++) acc[a][b] = 0ULL;
    for (int kk = 0; kk < K2; kk += 32) {
        __syncthreads();
        for (int idx = tid; idx < 2048; idx += 256) {
            int k = idx >> 6, j = idx & 63;
            int c = j >> 1, s = j & 1;
            int kg = kk + k;
            int col = c + 32 * s;
            float wv;
            if (kg < 800)      wv = w2b[kg * 64 + col];
            else if (kg < 832) wv = b2b[(kg - 800) * 64 + col];
            else               wv = root2[(kg - 832) * 64 + col];
            wsp[k * 64 + j] = wv;
        }
        for (int idx = tid; idx < 128 * 32; idx += 256) {
            int n = idx >> 5, kt = idx & 31;
            float tv = (nb + n < C1n) ? g_T2[(size_t)(nb + n) * T2S + kk + kt] : 0.f;
            td[kt * 130 + n] = make_float2(tv, tv);
        }
        __syncthreads();
#pragma unroll 8
        for (int k = 0; k < 32; k++) {
            ulonglong2 tA = *(const ulonglong2*)&td[k * 130 + n4];
            ulonglong2 tB = *(const ulonglong2*)&td[k * 130 + n4 + 2];
            ulonglong2 wA = *(const ulonglong2*)&wsp[k * 64 + c4 * 2];
            ulonglong2 wB = *(const ulonglong2*)&wsp[k * 64 + c4 * 2 + 4];
            ull tp[4] = {tA.x, tA.y, tB.x, tB.y};
            ull wp[4] = {wA.x, wA.y, wB.x, wB.y};
#pragma unroll
            for (int a = 0; a < 4; a++)
#pragma unroll
                for (int b = 0; b < 4; b++) acc[a][b] = fma2(tp[a], wp[b], acc[a][b]);
        }
    }
#pragma unroll
    for (int a = 0; a < 4; a++) {
        int n = nb + n4 + a;
        if (n >= C1n) continue;
        int c2 = cl2[n];
#pragma unroll
        for (int b = 0; b < 4; b++) {
            float lo, hi;
            unpack2f(lo, hi, acc[a][b]);
            float v0 = elu1(lo + bias2[c4 + b]);
            float v1 = elu1(hi + bias2[c4 + b + 32]);
            atomicMaxFloat(&gf.x3[c2 * 64 + c4 + b], v0);
            atomicMaxFloat(&gf.x3[c2 * 64 + c4 + b + 32], v1);
        }
        if (cg == 0) atomicMax(&gf.batch2[c2], max(gf.batchp[n], 0));
    }
}

// ---------------- K9: pool2 finalize + global mean scatter ----------------------
__global__ void k_pool2() {
    int c = (blockIdx.x * blockDim.x + threadIdx.x) >> 5;
    int lane = threadIdx.x & 31;
    if (c >= C2n) return;
    float v0 = fixneg(gf.x3[c * 64 + lane]);
    float v1 = fixneg(gf.x3[c * 64 + lane + 32]);
    int b = max(gf.batch2[c], 0);
    atomicAdd(&gz.gsum[b * 64 + lane], v0);
    atomicAdd(&gz.gsum[b * 64 + lane + 32], v1);
    if (lane == 0) atomicAdd(&gz.gcnt[b], 1.f);
}

// ---------------- K10: FC head + log_softmax ------------------------------------
__global__ void k_head(const float* __restrict__ fc1w, const float* __restrict__ fc1b,
                       const float* __restrict__ fc2w, const float* __restrict__ fc2b,
                       float* __restrict__ out) {
    __shared__ float g[16 * 64];
    __shared__ float hh[16 * 128];
    __shared__ float lg[16 * 10];
    int tid = threadIdx.x;
    for (int i = tid; i < 16 * 64; i += 256) g[i] = gz.gsum[i] / fmaxf(gz.gcnt[i >> 6], 1.f);
    __syncthreads();
    for (int o = tid; o < 16 * 128; o += 256) {
        int b = o >> 7, j = o & 127;
        float acc = fc1b[j];
        for (int k = 0; k < 64; k++) acc = fmaf(g[b * 64 + k], fc1w[k * 128 + j], acc);
        hh[o] = elu1(acc);
    }
    __syncthreads();
    if (tid < 160) {
        int b = tid / 10, k = tid % 10;
        float acc = fc2b[k];
        for (int j = 0; j < 128; j++) acc = fmaf(hh[b * 128 + j], fc2w[j * 10 + k], acc);
        lg[tid] = acc;
    }
    __syncthreads();
    if (tid < 16) {
        float m = -1e30f;
        for (int k = 0; k < 10; k++) m = fmaxf(m, lg[tid * 10 + k]);
        float s = 0.f;
        for (int k = 0; k < 10; k++) s += expf(lg[tid * 10 + k] - m);
        float ls = logf(s) + m;
        for (int k = 0; k < 10; k++) out[tid * 10 + k] = lg[tid * 10 + k] - ls;
    }
}

// ---------------- host launcher --------------------------------------------------
extern "C" void kernel_launch(void* const* d_in, const int* in_sizes, int n_in,
                              void* d_out, int out_size) {
    const float *x, *ea, *pos, *w1a, *b1a, *w1b, *b1b, *root1, *bias1;
    const float *w2a, *b2a, *w2b, *b2b, *root2, *bias2, *fc1w, *fc1b, *fc2w, *fc2b;
    const int *ei, *batch, *cl1, *ei2, *cl2;

    if (in_sizes[3] == 2 * Ee) {
        x = (const float*)d_in[0];  ea = (const float*)d_in[1];  pos = (const float*)d_in[2];
        ei = (const int*)d_in[3];   batch = (const int*)d_in[4]; cl1 = (const int*)d_in[5];
        ei2 = (const int*)d_in[6];  cl2 = (const int*)d_in[7];
        w1a = (const float*)d_in[8];  b1a = (const float*)d_in[9];
        w1b = (const float*)d_in[10]; b1b = (const float*)d_in[11];
        root1 = (const float*)d_in[12]; bias1 = (const float*)d_in[13];
        w2a = (const float*)d_in[14]; b2a = (const float*)d_in[15];
        w2b = (const float*)d_in[16]; b2b = (const float*)d_in[17];
        root2 = (const float*)d_in[18]; bias2 = (const float*)d_in[19];
        fc1w = (const float*)d_in[20]; fc1b = (const float*)d_in[21];
        fc2w = (const float*)d_in[22]; fc2b = (const float*)d_in[23];
    } else {
        x = (const float*)d_in[0];  ea = (const float*)d_in[1];  pos = (const float*)d_in[2];
        w1a = (const float*)d_in[3];  b1a = (const float*)d_in[4];
        w1b = (const float*)d_in[5];  b1b = (const float*)d_in[6];
        root1 = (const float*)d_in[7]; bias1 = (const float*)d_in[8];
        w2a = (const float*)d_in[9];  b2a = (const float*)d_in[10];
        w2b = (const float*)d_in[11]; b2b = (const float*)d_in[12];
        root2 = (const float*)d_in[13]; bias2 = (const float*)d_in[14];
        fc1w = (const float*)d_in[15]; fc1b = (const float*)d_in[16];
        fc2w = (const float*)d_in[17]; fc2b = (const float*)d_in[18];
        ei = (const int*)d_in[19];  batch = (const int*)d_in[20]; cl1 = (const int*)d_in[21];
        ei2 = (const int*)d_in[22]; cl2 = (const int*)d_in[23];
    }

    void *pz = nullptr, *pf = nullptr;
    cudaGetSymbolAddress(&pz, gz);
    cudaGetSymbolAddress(&pf, gf);
    cudaMemsetAsync(pz, 0, sizeof(ZBlk));
    cudaMemsetAsync(pf, 0xff, sizeof(FBlk));

    k_hist<<<(Ee + 255) / 256, 256>>>(ei, ei2, cl1, pos, batch);
    k_scan<<<2, 1024>>>();
    k_scat<<<(Ee + 255) / 256, 256>>>(ei, ei2, ea);
    k_conv1<<<3750, 256>>>(x, w1a, b1a);
    k_gemm1<<<(Nn + 127) / 128, 256>>>(w1b, b1b, root1, bias1, cl1);
    k_maxabs<<<(E2n + 255) / 256, 256>>>(ei2);
    k_conv2<<<1875, 256>>>(w2a, b2a);
    k_gemm2<<<(C1n + 127) / 128, 256>>>(w2b, b2b, root2, bias2, cl2);
    k_pool2<<<938, 256>>>();
    k_head<<<1, 256>>>(fc1w, fc1b, fc2w, fc2b, (float*)d_out);
}

// round 12
// speedup vs baseline: 1.3246x; 1.1836x over previous
#include <cuda_runtime.h>
#include <math.h>
#include <limits.h>

#define Nn 30000
#define Ee 400000
#define C1n 15000
#define E2n 100000
#define C2n 7500
#define Bn 16

#define T1S 168   // T1 row stride (162 used)
#define K1 162    // 150 w1b + 6 b1b + 6 root1
#define T2S 864   // T2 row stride
#define K2 864    // 800 w2b + 32 b2b + 32 root2

typedef unsigned long long ull;

// ---------------- zero-init block (single memset 0) ---------------------------
struct ZBlk {
    int   degD1[Nn];
    int   degD2[C1n], cntc1[C1n];
    float possum[C1n * 3];
    float gsum[Bn * 64];
    float gcnt[Bn];
    float maxabs;
};
// ---------------- 0xff-init block (single memset 0xff) ------------------------
struct FBlk {
    float xp[C1n * 32];      // 0xffffffff sentinel (loses to all atomicMaxFloat)
    float x3[C2n * 64];
    int   batchp[C1n];       // -1
    int   batch2[C2n];       // -1
};
__device__ ZBlk gz;
__device__ FBlk gf;

// ---------------- uninitialized scratch ----------------------------------------
__device__ int g_offD1[Nn + 1], g_curD1[Nn];
__device__ int g_offD2[C1n + 1], g_curD2[C1n];
__device__ __align__(16) float4 g_e4[Ee];          // {ea0,ea1,ea2, src-bits} dst-sorted
__device__ int g_csrD2s[E2n];                      // src ids dst-sorted
__device__ __align__(16) float g_T1[(size_t)Nn * T1S];
__device__ __align__(16) float g_T2[(size_t)C1n * T2S];

__device__ __forceinline__ void atomicMaxFloat(float* addr, float val) {
    if (val >= 0.f) atomicMax((int*)addr, __float_as_int(val));
    else            atomicMin((unsigned int*)addr, __float_as_uint(val));
}
__device__ __forceinline__ float elu1(float v) { return v > 0.f ? v : expm1f(v); }
__device__ __forceinline__ float fixneg(float v) { return (v > -3e38f) ? v : 0.f; }

// ---------------- K1: histograms + pool-input scatters --------------------------
__global__ void k_hist(const int* __restrict__ ei, const int* __restrict__ ei2,
                       const int* __restrict__ cl1, const float* __restrict__ pos,
                       const int* __restrict__ batch) {
    int t = blockIdx.x * blockDim.x + threadIdx.x;
    if (t < Ee)  atomicAdd(&gz.degD1[ei[Ee + t]], 1);
    if (t < E2n) atomicAdd(&gz.degD2[ei2[E2n + t]], 1);
    if (t < Nn) {
        int c = cl1[t];
        atomicAdd(&gz.cntc1[c], 1);
        atomicAdd(&gz.possum[c * 3],     pos[t * 3]);
        atomicAdd(&gz.possum[c * 3 + 1], pos[t * 3 + 1]);
        atomicAdd(&gz.possum[c * 3 + 2], pos[t * 3 + 2]);
        atomicMax(&gf.batchp[c], batch[t]);
    }
}

// ---------------- K2: exclusive scans (2 arrays, 4 elems/thread) ----------------
__global__ void k_scan() {
    const int* deg; int* off; int* cur; int n;
    if (blockIdx.x == 0) { deg = gz.degD1; off = g_offD1; cur = g_curD1; n = Nn; }
    else                 { deg = gz.degD2; off = g_offD2; cur = g_curD2; n = C1n; }
    __shared__ int wsum[32];
    __shared__ int carry;
    int tid = threadIdx.x, lane = tid & 31, wid = tid >> 5;
    if (tid == 0) carry = 0;
    __syncthreads();
    for (int base = 0; base < n; base += 4096) {
        int i0 = base + tid * 4;
        int v[4];
#pragma unroll
        for (int k = 0; k < 4; k++) v[k] = (i0 + k < n) ? deg[i0 + k] : 0;
        int s = v[0] + v[1] + v[2] + v[3];
        int incl = s;
#pragma unroll
        for (int o = 1; o < 32; o <<= 1) {
            int tt = __shfl_up_sync(0xffffffffu, incl, o);
            if (lane >= o) incl += tt;
        }
        if (lane == 31) wsum[wid] = incl;
        __syncthreads();
        if (wid == 0) {
            int t2 = wsum[lane];
#pragma unroll
            for (int o = 1; o < 32; o <<= 1) {
                int tt = __shfl_up_sync(0xffffffffu, t2, o);
                if (lane >= o) t2 += tt;
            }
            wsum[lane] = t2;
        }
        __syncthreads();
        int woff = (wid == 0) ? 0 : wsum[wid - 1];
        int run = carry + woff + incl - s;
#pragma unroll
        for (int k = 0; k < 4; k++) {
            if (i0 + k < n) { off[i0 + k] = run; cur[i0 + k] = run; }
            run += v[k];
        }
        __syncthreads();
        if (tid == 0) carry += wsum[31];
        __syncthreads();
    }
    if (threadIdx.x == 0) off[n] = carry;
}

// ---------------- K3: scatter + fused maxabs ------------------------------------
__global__ void k_scat(const int* __restrict__ ei, const int* __restrict__ ei2,
                       const float* __restrict__ ea) {
    int t = blockIdx.x * blockDim.x + threadIdx.x;
    if (t < Ee) {
        int p = atomicAdd(&g_curD1[ei[Ee + t]], 1);
        float4 v;
        v.x = ea[3 * t]; v.y = ea[3 * t + 1]; v.z = ea[3 * t + 2];
        v.w = __int_as_float(ei[t]);
        g_e4[p] = v;
    }
    float m = 0.f;
    if (t < E2n) {
        int s = ei2[t], d = ei2[E2n + t];
        int p = atomicAdd(&g_curD2[d], 1);
        g_csrD2s[p] = s;
        float is = 1.f / fmaxf((float)gz.cntc1[s], 1.f);
        float id = 1.f / fmaxf((float)gz.cntc1[d], 1.f);
#pragma unroll
        for (int k = 0; k < 3; k++)
            m = fmaxf(m, fabsf(gz.possum[s * 3 + k] * is - gz.possum[d * 3 + k] * id));
    }
#pragma unroll
    for (int o = 16; o; o >>= 1) m = fmaxf(m, __shfl_xor_sync(0xffffffffu, m, o));
    if ((threadIdx.x & 31) == 0 && m > 0.f) atomicMax((int*)&gz.maxabs, __float_as_int(m));
}

// ---------------- K4: conv1 edge pass -> T1 (warp per dst node) -----------------
__global__ void __launch_bounds__(256) k_conv1(
        const float* __restrict__ x,
        const float* __restrict__ w1a, const float* __restrict__ b1a) {
    int tid = threadIdx.x;
    int d = (blockIdx.x * blockDim.x + tid) >> 5;
    int lane = tid & 31;
    if (d >= Nn) return;
    float wa0 = 0.f, wa1 = 0.f, wa2 = 0.f, ba = 0.f;
    if (lane < 25) { wa0 = w1a[lane]; wa1 = w1a[25 + lane]; wa2 = w1a[50 + lane]; ba = b1a[lane]; }
    else if (lane == 25) ba = 1.f;   // h == 1 -> x-sum (bias) row
    float acc0 = 0.f, acc1 = 0.f, acc2 = 0.f, acc3 = 0.f, acc4 = 0.f, acc5 = 0.f;
    int p0 = g_offD1[d], p1 = g_offD1[d + 1];
    for (int p = p0; p < p1; p++) {
        float4 e4 = g_e4[p];
        int src = __float_as_int(e4.w);
        const float2* xs = (const float2*)(x + src * 6);
        float2 x01 = xs[0], x23 = xs[1], x45 = xs[2];
        float h = fmaxf(fmaf(e4.x, wa0, fmaf(e4.y, wa1, fmaf(e4.z, wa2, ba))), 0.f);
        acc0 = fmaf(h, x01.x, acc0); acc1 = fmaf(h, x01.y, acc1);
        acc2 = fmaf(h, x23.x, acc2); acc3 = fmaf(h, x23.y, acc3);
        acc4 = fmaf(h, x45.x, acc4); acc5 = fmaf(h, x45.y, acc5);
    }
    float invd = 1.f / fmaxf((float)(p1 - p0), 1.f);
    float* Trow = g_T1 + (size_t)d * T1S + lane * 6;
    if (lane < 26) {
        Trow[0] = acc0 * invd; Trow[1] = acc1 * invd; Trow[2] = acc2 * invd;
        Trow[3] = acc3 * invd; Trow[4] = acc4 * invd; Trow[5] = acc5 * invd;
    } else if (lane == 26) {
#pragma unroll
        for (int i = 0; i < 6; i++) Trow[i] = x[d * 6 + i];
    }
}

// ---------------- K5: gemm1  out = T1 @ [w1b|b1b|root1] + bias1 -> elu -> pool1 --
__global__ void __launch_bounds__(256) k_gemm1(
        const float* __restrict__ w1b, const float* __restrict__ b1b,
        const float* __restrict__ root1, const float* __restrict__ bias1,
        const int* __restrict__ cl1) {
    __shared__ __align__(16) float Ws[192 * 32];
    __shared__ __align__(16) float Ts[32 * 136];
    int tid = threadIdx.x;
    int nb = blockIdx.x * 128;
    for (int idx = tid; idx < 192 * 32; idx += 256) {
        float v = 0.f;
        if (idx < 4800)      v = w1b[idx];
        else if (idx < 4992) v = b1b[idx - 4800];
        else if (idx < 5184) v = root1[idx - 4992];
        Ws[idx] = v;
    }
    int cg = tid & 7, ng = tid >> 3;
    int c4 = cg * 4, n4 = ng * 4;
    float acc[4][4];
#pragma unroll
    for (int a = 0; a < 4; a++)
#pragma unroll
        for (int b = 0; b < 4; b++) acc[a][b] = 0.f;
    for (int kk = 0; kk < K1; kk += 32) {
        __syncthreads();
        for (int idx = tid; idx < 128 * 32; idx += 256) {
            int n = idx >> 5, k = idx & 31;
            float v = 0.f;
            if (kk + k < K1 && nb + n < Nn) v = g_T1[(size_t)(nb + n) * T1S + kk + k];
            Ts[k * 136 + n] = v;
        }
        __syncthreads();
#pragma unroll 8
        for (int k = 0; k < 32; k++) {
            float4 tv = *(const float4*)&Ts[k * 136 + n4];
            float4 wv = *(const float4*)&Ws[(kk + k) * 32 + c4];
            float ta[4] = {tv.x, tv.y, tv.z, tv.w};
            float wa[4] = {wv.x, wv.y, wv.z, wv.w};
#pragma unroll
            for (int a = 0; a < 4; a++)
#pragma unroll
                for (int b = 0; b < 4; b++) acc[a][b] = fmaf(ta[a], wa[b], acc[a][b]);
        }
    }
#pragma unroll
    for (int a = 0; a < 4; a++) {
        int n = nb + n4 + a;
        if (n >= Nn) continue;
        int c = cl1[n];
#pragma unroll
        for (int b = 0; b < 4; b++) {
            float v = elu1(acc[a][b] + bias1[c4 + b]);
            atomicMaxFloat(&gf.xp[c * 32 + c4 + b], v);
        }
    }
}

// ---------------- K6: conv2 edge pass -> T2 (warp per dst C1 node) ---------------
__global__ void __launch_bounds__(256) k_conv2(
        const float* __restrict__ w2a, const float* __restrict__ b2a) {
    int tid = threadIdx.x;
    int d = (blockIdx.x * blockDim.x + tid) >> 5;
    int lane = tid & 31;
    if (d >= C1n) return;
    float wa0 = 0.f, wa1 = 0.f, wa2 = 0.f, ba = 0.f;
    if (lane < 25) { wa0 = w2a[lane]; wa1 = w2a[25 + lane]; wa2 = w2a[50 + lane]; ba = b2a[lane]; }
    else if (lane == 25) ba = 1.f;
    float invcd = 1.f / fmaxf((float)gz.cntc1[d], 1.f);
    float pd0 = gz.possum[d * 3] * invcd, pd1 = gz.possum[d * 3 + 1] * invcd,
          pd2 = gz.possum[d * 3 + 2] * invcd;
    float inv = 0.5f / gz.maxabs;
    float acc[26];
#pragma unroll
    for (int r = 0; r < 26; r++) acc[r] = 0.f;
    int p0 = g_offD2[d], p1 = g_offD2[d + 1];
    for (int p = p0; p < p1; p++) {
        int src = g_csrD2s[p];
        float invcs = 1.f / fmaxf((float)gz.cntc1[src], 1.f);
        float e0 = fmaf(gz.possum[src * 3] * invcs - pd0,     inv, 0.5f);
        float e1 = fmaf(gz.possum[src * 3 + 1] * invcs - pd1, inv, 0.5f);
        float e2 = fmaf(gz.possum[src * 3 + 2] * invcs - pd2, inv, 0.5f);
        float h = fmaxf(fmaf(e0, wa0, fmaf(e1, wa1, fmaf(e2, wa2, ba))), 0.f);
        float xpi = fixneg(gf.xp[src * 32 + lane]);
#pragma unroll
        for (int r = 0; r < 26; r++) {
            float hr = __shfl_sync(0xffffffffu, h, r);
            acc[r] = fmaf(hr, xpi, acc[r]);
        }
    }
    float invd = 1.f / fmaxf((float)(p1 - p0), 1.f);
    float* Trow = g_T2 + (size_t)d * T2S;
#pragma unroll
    for (int r = 0; r < 26; r++) Trow[r * 32 + lane] = acc[r] * invd;
    Trow[832 + lane] = fixneg(gf.xp[d * 32 + lane]);   // root columns
}

// ---------------- K7: gemm2 scalar (R8-proven)  -----------------------------------
__global__ void __launch_bounds__(256) k_gemm2(
        const float* __restrict__ w2b, const float* __restrict__ b2b,
        const float* __restrict__ root2, const float* __restrict__ bias2,
        const int* __restrict__ cl2) {
    __shared__ __align__(16) float Ws[64 * 64];
    __shared__ __align__(16) float Ts[64 * 68];
    int tid = threadIdx.x;
    int nb = blockIdx.x * 64;
    int cg = tid & 15, ng = tid >> 4;
    int c4 = cg * 4, n4 = ng * 4;
    float acc[4][4];
#pragma unroll
    for (int a = 0; a < 4; a++)
#pragma unroll
        for (int b = 0; b < 4; b++) acc[a][b] = 0.f;
    for (int kk = 0; kk < K2; kk += 64) {
        __syncthreads();
        for (int idx = tid; idx < 64 * 64; idx += 256) {
            int kr = idx >> 6, c = idx & 63;
            int k = kk + kr;
            float v;
            if (k < 800)      v = w2b[k * 64 + c];
            else if (k < 832) v = b2b[(k - 800) * 64 + c];
            else              v = root2[(k - 832) * 64 + c];
            Ws[idx] = v;
            int n = idx >> 6, kt = idx & 63;
            float tv = 0.f;
            if (nb + n < C1n) tv = g_T2[(size_t)(nb + n) * T2S + kk + kt];
            Ts[kt * 68 + n] = tv;
        }
        __syncthreads();
#pragma unroll 8
        for (int k = 0; k < 64; k++) {
            float4 tv = *(const float4*)&Ts[k * 68 + n4];
            float4 wv = *(const float4*)&Ws[k * 64 + c4];
            float ta[4] = {tv.x, tv.y, tv.z, tv.w};
            float wa[4] = {wv.x, wv.y, wv.z, wv.w};
#pragma unroll
            for (int a = 0; a < 4; a++)
#pragma unroll
                for (int b = 0; b < 4; b++) acc[a][b] = fmaf(ta[a], wa[b], acc[a][b]);
        }
    }
#pragma unroll
    for (int a = 0; a < 4; a++) {
        int n = nb + n4 + a;
        if (n >= C1n) continue;
        int c2 = cl2[n];
#pragma unroll
        for (int b = 0; b < 4; b++) {
            float v = elu1(acc[a][b] + bias2[c4 + b]);
            atomicMaxFloat(&gf.x3[c2 * 64 + c4 + b], v);
        }
        if (cg == 0) atomicMax(&gf.batch2[c2], max(gf.batchp[n], 0));
    }
}

// ---------------- K8: pool2 finalize + global mean scatter ----------------------
__global__ void k_pool2() {
    int c = (blockIdx.x * blockDim.x + threadIdx.x) >> 5;
    int lane = threadIdx.x & 31;
    if (c >= C2n) return;
    float v0 = fixneg(gf.x3[c * 64 + lane]);
    float v1 = fixneg(gf.x3[c * 64 + lane + 32]);
    int b = max(gf.batch2[c], 0);
    atomicAdd(&gz.gsum[b * 64 + lane], v0);
    atomicAdd(&gz.gsum[b * 64 + lane + 32], v1);
    if (lane == 0) atomicAdd(&gz.gcnt[b], 1.f);
}

// ---------------- K9: FC head + log_softmax ------------------------------------
__global__ void k_head(const float* __restrict__ fc1w, const float* __restrict__ fc1b,
                       const float* __restrict__ fc2w, const float* __restrict__ fc2b,
                       float* __restrict__ out) {
    __shared__ float g[16 * 64];
    __shared__ float hh[16 * 128];
    __shared__ float lg[16 * 10];
    int tid = threadIdx.x;
    for (int i = tid; i < 16 * 64; i += 256) g[i] = gz.gsum[i] / fmaxf(gz.gcnt[i >> 6], 1.f);
    __syncthreads();
    for (int o = tid; o < 16 * 128; o += 256) {
        int b = o >> 7, j = o & 127;
        float acc = fc1b[j];
        for (int k = 0; k < 64; k++) acc = fmaf(g[b * 64 + k], fc1w[k * 128 + j], acc);
        hh[o] = elu1(acc);
    }
    __syncthreads();
    if (tid < 160) {
        int b = tid / 10, k = tid % 10;
        float acc = fc2b[k];
        for (int j = 0; j < 128; j++) acc = fmaf(hh[b * 128 + j], fc2w[j * 10 + k], acc);
        lg[tid] = acc;
    }
    __syncthreads();
    if (tid < 16) {
        float m = -1e30f;
        for (int k = 0; k < 10; k++) m = fmaxf(m, lg[tid * 10 + k]);
        float s = 0.f;
        for (int k = 0; k < 10; k++) s += expf(lg[tid * 10 + k] - m);
        float ls = logf(s) + m;
        for (int k = 0; k < 10; k++) out[tid * 10 + k] = lg[tid * 10 + k] - ls;
    }
}

// ---------------- host launcher --------------------------------------------------
extern "C" void kernel_launch(void* const* d_in, const int* in_sizes, int n_in,
                              void* d_out, int out_size) {
    const float *x, *ea, *pos, *w1a, *b1a, *w1b, *b1b, *root1, *bias1;
    const float *w2a, *b2a, *w2b, *b2b, *root2, *bias2, *fc1w, *fc1b, *fc2w, *fc2b;
    const int *ei, *batch, *cl1, *ei2, *cl2;

    if (in_sizes[3] == 2 * Ee) {
        x = (const float*)d_in[0];  ea = (const float*)d_in[1];  pos = (const float*)d_in[2];
        ei = (const int*)d_in[3];   batch = (const int*)d_in[4]; cl1 = (const int*)d_in[5];
        ei2 = (const int*)d_in[6];  cl2 = (const int*)d_in[7];
        w1a = (const float*)d_in[8];  b1a = (const float*)d_in[9];
        w1b = (const float*)d_in[10]; b1b = (const float*)d_in[11];
        root1 = (const float*)d_in[12]; bias1 = (const float*)d_in[13];
        w2a = (const float*)d_in[14]; b2a = (const float*)d_in[15];
        w2b = (const float*)d_in[16]; b2b = (const float*)d_in[17];
        root2 = (const float*)d_in[18]; bias2 = (const float*)d_in[19];
        fc1w = (const float*)d_in[20]; fc1b = (const float*)d_in[21];
        fc2w = (const float*)d_in[22]; fc2b = (const float*)d_in[23];
    } else {
        x = (const float*)d_in[0];  ea = (const float*)d_in[1];  pos = (const float*)d_in[2];
        w1a = (const float*)d_in[3];  b1a = (const float*)d_in[4];
        w1b = (const float*)d_in[5];  b1b = (const float*)d_in[6];
        root1 = (const float*)d_in[7]; bias1 = (const float*)d_in[8];
        w2a = (const float*)d_in[9];  b2a = (const float*)d_in[10];
        w2b = (const float*)d_in[11]; b2b = (const float*)d_in[12];
        root2 = (const float*)d_in[13]; bias2 = (const float*)d_in[14];
        fc1w = (const float*)d_in[15]; fc1b = (const float*)d_in[16];
        fc2w = (const float*)d_in[17]; fc2b = (const float*)d_in[18];
        ei = (const int*)d_in[19];  batch = (const int*)d_in[20]; cl1 = (const int*)d_in[21];
        ei2 = (const int*)d_in[22]; cl2 = (const int*)d_in[23];
    }

    void *pz = nullptr, *pf = nullptr;
    cudaGetSymbolAddress(&pz, gz);
    cudaGetSymbolAddress(&pf, gf);
    cudaMemsetAsync(pz, 0, sizeof(ZBlk));
    cudaMemsetAsync(pf, 0xff, sizeof(FBlk));

    k_hist<<<(Ee + 255) / 256, 256>>>(ei, ei2, cl1, pos, batch);
    k_scan<<<2, 1024>>>();
    k_scat<<<(Ee + 255) / 256, 256>>>(ei, ei2, ea);
    k_conv1<<<3750, 256>>>(x, w1a, b1a);
    k_gemm1<<<(Nn + 127) / 128, 256>>>(w1b, b1b, root1, bias1, cl1);
    k_conv2<<<1875, 256>>>(w2a, b2a);
    k_gemm2<<<(C1n + 63) / 64, 256>>>(w2b, b2b, root2, bias2, cl2);
    k_pool2<<<938, 256>>>();
    k_head<<<1, 256>>>(fc1w, fc1b, fc2w, fc2b, (float*)d_out);
}